// round 8
// baseline (speedup 1.0000x reference)
#include <cuda_runtime.h>
#include <cstdint>

// LatticeSnake: B=32, L=512, W=9. Output [B, L, 9,9,9, 1] fp32 (48 MB).
// Doubled walk coords (the 2(L-1) grid offset cancels):
//   residue j:   p = 2*idx[j],         v = acids[j]*mask[j]
//   midpoint k:  p = idx[k]+idx[k+1],  v = (acids[k]+acids[k+1]+1)*mask[k+1]
//   voxel (i,r): value = sum of points at p == 2*idx[i] + r - 4
//
// R8 = R7 gather-grid, tuned for single-wave residency:
//   - smem ~30.8 KB (coords as int16, values read lazily from global)
//   - __launch_bounds__(256,7): 7 CTAs/SM -> all 1024 CTAs in ONE wave
//   - bbox + window bases computed once by warp 0 (shfl reduce) while
//     warps 1-7 stage coords; zeroing overlaps both
//   - gather: per voxel one LDS + one coalesced STG.32, no output atomics

#define LS_L    512
#define LS_W    9
#define LS_W3   729
#define LS_R    16               // windows per CTA
#define LS_NT   256
#define LS_NG   (LS_L / LS_R)    // 32 groups per batch
#define LS_M    (2 * LS_L - 1)   // 1023 snake points
#define GRIDPAD 6912             // >= worst-case vol 19^3 = 6859, mult of 4

__global__ __launch_bounds__(LS_NT, 7)
void lattice_snake_kernel(const float* __restrict__ acids,
                          const float* __restrict__ mask,
                          const int*   __restrict__ idx,
                          float*       __restrict__ out)
{
    __shared__ alignas(16) float grid[GRIDPAD];   // 27648 B
    __shared__ short sidx[LS_L * 3];              //  3072 B (coords, int16)
    __shared__ int   sAw[LS_R];                   // per-window grid base cell
    __shared__ int   sBB[6];                      // gxl,gyl,gzl,sx,sy,sz

    const int b   = blockIdx.x >> 5;            // / LS_NG
    const int g   = blockIdx.x & (LS_NG - 1);
    const int i0  = g * LS_R;
    const int tid = threadIdx.x;

    const int*   gi = idx   + (size_t)b * LS_L * 3;
    const float* ga = acids + (size_t)b * LS_L;
    const float* gm = mask  + (size_t)b * LS_L;
    float* gout = out + (size_t)(b * LS_L + i0) * LS_W3;

    // ---- zero full worst-case grid (no dependency on bbox) ----
    {
        float4* g4 = reinterpret_cast<float4*>(grid);
        const float4 z = make_float4(0.f, 0.f, 0.f, 0.f);
        #pragma unroll
        for (int e = tid; e < GRIDPAD / 4; e += LS_NT) g4[e] = z;
    }

    if (tid < 32) {
        // ---- warp 0: bbox over 16 centers + per-window base cells ----
        const int r  = tid & 15;                 // lanes 16-31 duplicate
        const int jj = 3 * (i0 + r);
        const int cx = 2 * gi[jj + 0];
        const int cy = 2 * gi[jj + 1];
        const int cz = 2 * gi[jj + 2];
        int xmin = cx, xmax = cx, ymin = cy, ymax = cy, zmin = cz, zmax = cz;
        #pragma unroll
        for (int d = 8; d >= 1; d >>= 1) {
            xmin = min(xmin, __shfl_xor_sync(0xffffffffu, xmin, d));
            xmax = max(xmax, __shfl_xor_sync(0xffffffffu, xmax, d));
            ymin = min(ymin, __shfl_xor_sync(0xffffffffu, ymin, d));
            ymax = max(ymax, __shfl_xor_sync(0xffffffffu, ymax, d));
            zmin = min(zmin, __shfl_xor_sync(0xffffffffu, zmin, d));
            zmax = max(zmax, __shfl_xor_sync(0xffffffffu, zmax, d));
        }
        const int syv = ymax - ymin + 9;
        const int szv = zmax - zmin + 9;
        // window r's voxel (0,0,0) is cell (2c - 4 - (min-4)) = 2c - min
        if (tid < 16)
            sAw[tid] = ((cx - xmin) * syv + (cy - ymin)) * szv + (cz - zmin);
        if (tid == 0) {
            sBB[0] = xmin - 4; sBB[1] = ymin - 4; sBB[2] = zmin - 4;
            sBB[3] = xmax - xmin + 9; sBB[4] = syv; sBB[5] = szv;
        }
    } else {
        // ---- warps 1-7: stage coords to int16 smem (range fits: |2c|<=2044)
        for (int e = tid - 32; e < LS_L * 3; e += LS_NT - 32)
            sidx[e] = (short)gi[e];
    }
    __syncthreads();

    const int gxl = sBB[0], gyl = sBB[1], gzl = sBB[2];
    const int sx  = sBB[3], sy  = sBB[4], sz  = sBB[5];

    // ---- scan 1023 points; bbox hits accumulate into grid (smem atomics).
    // rounds 0-1 are residues, 2-3 midpoints: warp-uniform type branch.
    #pragma unroll
    for (int rnd = 0; rnd < 4; rnd++) {
        const int j = tid + rnd * LS_NT;
        if (j < LS_M) {
            int px, py, pz;
            int k = j;
            if (j < LS_L) {
                const int jj = 3 * j;
                px = 2 * (int)sidx[jj + 0];
                py = 2 * (int)sidx[jj + 1];
                pz = 2 * (int)sidx[jj + 2];
            } else {
                k = j - LS_L;                    // 0 .. L-2
                const int jj = 3 * k;
                px = (int)sidx[jj + 0] + (int)sidx[jj + 3];
                py = (int)sidx[jj + 1] + (int)sidx[jj + 4];
                pz = (int)sidx[jj + 2] + (int)sidx[jj + 5];
            }
            const unsigned ux = (unsigned)(px - gxl);
            const unsigned uy = (unsigned)(py - gyl);
            const unsigned uz = (unsigned)(pz - gzl);
            if (ux < (unsigned)sx && uy < (unsigned)sy && uz < (unsigned)sz) {
                // lazy value load: only bbox survivors touch acids/mask
                const float v = (j < LS_L)
                    ? ga[k] * gm[k]
                    : (ga[k] + ga[k + 1] + 1.0f) * gm[k + 1];
                atomicAdd(&grid[(ux * sy + uy) * sz + uz], v);
            }
        }
    }
    __syncthreads();   // grid complete

    // ---- gather: voxel = one LDS + one coalesced STG.32 ----
    int relOff0, relOff1, relOff2;
    {
        #pragma unroll
        for (int kk = 0; kk < 3; kk++) {
            const int lin = tid + kk * LS_NT;
            const int rx  = lin / 81;
            const int rem = lin - rx * 81;
            const int ry  = rem / 9;
            const int rz  = rem - ry * 9;
            const int off = (rx * sy + ry) * sz + rz;
            if (kk == 0) relOff0 = off;
            else if (kk == 1) relOff1 = off;
            else relOff2 = off;
        }
    }
    const bool k2ok = tid < (LS_W3 - 2 * LS_NT);   // 729-512 = 217
    #pragma unroll
    for (int w = 0; w < LS_R; w++) {
        const int Aw = sAw[w];                     // broadcast LDS
        float* gw = gout + w * LS_W3;
        gw[tid]             = grid[Aw + relOff0];
        gw[tid + LS_NT]     = grid[Aw + relOff1];
        if (k2ok) gw[tid + 2 * LS_NT] = grid[Aw + relOff2];
    }
}

extern "C" void kernel_launch(void* const* d_in, const int* in_sizes, int n_in,
                              void* d_out, int out_size)
{
    const float* acids = (const float*)d_in[0];   // [B, L]
    const float* mask  = (const float*)d_in[1];   // [B, L]
    const int*   idx   = (const int*)  d_in[2];   // [B, L, 3]
    float*       out   = (float*)d_out;           // [B, L, 9,9,9, 1]

    const int nB = in_sizes[0] / LS_L;            // 32
    lattice_snake_kernel<<<nB * LS_NG, LS_NT>>>(acids, mask, idx, out);
}